// round 11
// baseline (speedup 1.0000x reference)
#include <cuda_runtime.h>
#include <cstdint>

#define BATCH 2
#define NPTS 8192
#define IMGS 64
#define KSEL 8
#define RAD2 0.0025f
#define RADM 0.0501f            // conservative bbox radius
#define NPIX (BATCH * IMGS * IMGS)   // 8192
#define CAP 256                 // per-pixel capacity (hot pixel ~150; +13 sigma)

// Static scratch (allocation-free). BSS-zero at load; select_k restores
// g_cnt to zero every launch (graph-replay invariant).
__device__ float4 g_screen[BATCH * NPTS];
__device__ int g_cnt[NPIX];
__device__ ulonglong2 g_plist[(size_t)NPIX * CAP];   // {key, d2bits} — 32 MB

// ---------------------------------------------------------------------------
// Kernel A: project + scatter. EIGHT lanes per point, each owns a 1x2 sub-row
// of the 4x4 bbox. Single exit path ending in griddepcontrol.launch_dependents
// so the PDL-launched select_k can release as soon as all stores are issued.
// ---------------------------------------------------------------------------
__global__ __launch_bounds__(256) void project_scatter(const float* __restrict__ pts,
                                                       const float* __restrict__ Rm,
                                                       const float* __restrict__ Tv,
                                                       const float* __restrict__ focal) {
    const int gt = blockIdx.x * 256 + threadIdx.x;   // 0..131071
    const int t = gt >> 3;                           // point id 0..16383
    const int sub = gt & 7;
    const int row = sub >> 1;                        // bbox row 0..3
    const int ch = (sub & 1) << 1;                   // bbox col pair: 0 or 2
    const int b = t >> 13;
    const int n = t & (NPTS - 1);
    const float* p = pts + (size_t)t * 3;
    const float* R = Rm + b * 9;
    const float* T = Tv + b * 3;
    float p0 = p[0], p1 = p[1], p2 = p[2];

    float v0 = __fmaf_rn(p2, R[6], __fmaf_rn(p1, R[3], __fmul_rn(p0, R[0])));
    float v1 = __fmaf_rn(p2, R[7], __fmaf_rn(p1, R[4], __fmul_rn(p0, R[1])));
    float v2 = __fmaf_rn(p2, R[8], __fmaf_rn(p1, R[5], __fmul_rn(p0, R[2])));
    v0 = __fadd_rn(v0, T[0]);
    v1 = __fadd_rn(v1, T[1]);
    float z = __fadd_rn(v2, T[2]);

    float x = -__fdiv_rn(__fmul_rn(focal[0], v0), z);
    float y = -__fdiv_rn(__fmul_rn(focal[1], v1), z);
    if (sub == 0) g_screen[t] = make_float4(x, y, z, 0.0f);  // slow-path emit data

    if (z > 0.0f) {
        // pixel centers c(i) = 1 - (i+0.5)*0.03125, decreasing in i.
        int ix0 = (int)ceilf(__fmul_rn(1.0f - (x + RADM), 32.0f) - 0.5f);
        int ix1 = (int)floorf(__fmul_rn(1.0f - (x - RADM), 32.0f) - 0.5f);
        int iy0 = (int)ceilf(__fmul_rn(1.0f - (y + RADM), 32.0f) - 0.5f);
        int iy1 = (int)floorf(__fmul_rn(1.0f - (y - RADM), 32.0f) - 0.5f);
        ix0 = max(ix0, 0); ix1 = min(ix1, IMGS - 1);
        iy0 = max(iy0, 0); iy1 = min(iy1, IMGS - 1);

        const int iy = iy0 + row;                   // this lane's bbox row
        if (iy <= iy1) {
            const unsigned long long key =
                ((unsigned long long)__float_as_uint(z) << 32) | (unsigned)n;
            float py = 1.0f - ((float)iy + 0.5f) * 0.03125f;
            float dy = __fsub_rn(py, y);
            float dy2 = __fmul_rn(dy, dy);
#pragma unroll
            for (int c = 0; c < 2; ++c) {
                int ix = ix0 + ch + c;
                bool vx = ix <= ix1;
                float px = 1.0f - ((float)ix + 0.5f) * 0.03125f;
                float dx = __fsub_rn(px, x);
                float d2 = __fadd_rn(__fmul_rn(dx, dx), dy2);
                if (vx && d2 <= RAD2) {             // exact reference predicate
                    int pix = (b << 12) + (iy << 6) + ix;
                    int pos = atomicAdd(&g_cnt[pix], 1);
                    if (pos < CAP)
                        g_plist[(size_t)pix * CAP + pos] =
                            make_ulonglong2(key, (unsigned long long)__float_as_uint(d2));
                }
            }
        }
    }

    // PDL: signal dependent kernel once this thread's writes are issued.
    asm volatile("griddepcontrol.launch_dependents;" ::: "memory");
}

// ---------------------------------------------------------------------------
// Kernel B: one warp per pixel. cnt gates ALL list access: empty pixels never
// touch g_plist (kills the cold-DRAM-line traffic that capped R10), and
// partially-filled pixels only load written slots (predicated on lane < cnt).
//   cnt == 0   : -1 fill, no list load.
//   cnt <= 32  : rank selection, 1 key/lane.
//   cnt <= 64  : rank selection, 2 keys/lane.
//   cnt  > 64  : per-lane sorted top-8; REDUX-min merge; gather-based emit.
// Keys unique => (z, idx) ascending = jax top_k order exactly.
// ---------------------------------------------------------------------------
__global__ __launch_bounds__(256) void select_k(float* __restrict__ out) {
    const int warp = threadIdx.x >> 5;
    const int lane = threadIdx.x & 31;
    const int pix = blockIdx.x * 8 + warp;          // 0..NPIX-1
    const unsigned long long SENT = ~0ull;
    const unsigned FULL = 0xffffffffu;
    const size_t TSZ = (size_t)NPIX * KSEL;         // 65536
    const size_t o0 = (size_t)pix * KSEL;
    const ulonglong2* __restrict__ list = g_plist + (size_t)pix * CAP;

    // PDL: everything above is A-independent; block here before touching
    // g_cnt / g_plist (released by project_scatter's launch_dependents).
    asm volatile("griddepcontrol.wait;" ::: "memory");

    int cnt = min(g_cnt[pix], CAP);

    if (cnt == 0) {
        if (lane < KSEL) {
            out[o0 + lane] = -1.0f;
            out[TSZ + o0 + lane] = -1.0f;
            out[2 * TSZ + o0 + lane] = -1.0f;
        }
        return;                                     // g_cnt already 0
    }

    // Predicated load: lanes >= cnt issue no address (no cold lines).
    ulonglong2 rec = make_ulonglong2(SENT, 0);
    if (lane < cnt) rec = list[lane];

    if (cnt <= 32) {
        // ---- single-key rank selection (flat latency) ----
        unsigned long long myk = rec.x;             // SENT for lanes >= cnt
        int rank = 0;
        for (int c = 0; c < cnt; ++c) {             // warp-uniform bound
            unsigned long long kc = __shfl_sync(FULL, myk, c);
            rank += (kc < myk) ? 1 : 0;
        }
        if (lane < cnt && rank < KSEL) {
            out[o0 + rank] = (float)(unsigned)myk;                         // idx
            out[TSZ + o0 + rank] = __uint_as_float((unsigned)(myk >> 32)); // z
            out[2 * TSZ + o0 + rank] = __uint_as_float((unsigned)rec.y);   // d2
        }
        if (lane >= cnt && lane < KSEL) {           // unfilled slots
            out[o0 + lane] = -1.0f;
            out[TSZ + o0 + lane] = -1.0f;
            out[2 * TSZ + o0 + lane] = -1.0f;
        }
    } else if (cnt <= 64) {
        // ---- two-key rank selection ----
        unsigned long long k0 = rec.x;              // lane < 32 < cnt: valid
        unsigned long long k1 = SENT;
        unsigned d1bits = 0;
        if (lane + 32 < cnt) {
            ulonglong2 rec2 = list[lane + 32];
            k1 = rec2.x;
            d1bits = (unsigned)rec2.y;
        }
        int r0 = 0, r1 = 0;
#pragma unroll 4
        for (int c = 0; c < 32; ++c) {
            unsigned long long kc = __shfl_sync(FULL, k0, c);
            r0 += (kc < k0) ? 1 : 0;
            r1 += (kc < k1) ? 1 : 0;
        }
        for (int c = 32; c < cnt; ++c) {
            unsigned long long kc = __shfl_sync(FULL, k1, c - 32);
            r0 += (kc < k0) ? 1 : 0;
            r1 += (kc < k1) ? 1 : 0;
        }
        // cnt > 8 => ranks 0..7 all occupied; no fill needed.
        if (r0 < KSEL) {
            out[o0 + r0] = (float)(unsigned)k0;
            out[TSZ + o0 + r0] = __uint_as_float((unsigned)(k0 >> 32));
            out[2 * TSZ + o0 + r0] = __uint_as_float((unsigned)rec.y);
        }
        if (lane + 32 < cnt && r1 < KSEL) {
            out[o0 + r1] = (float)(unsigned)k1;
            out[TSZ + o0 + r1] = __uint_as_float((unsigned)(k1 >> 32));
            out[2 * TSZ + o0 + r1] = __uint_as_float(d1bits);
        }
    } else {
        // ---- per-lane sorted top-8 over strided scan ----
        unsigned long long key[KSEL];
#pragma unroll
        for (int i = 0; i < KSEL; ++i) key[i] = SENT;
        key[0] = rec.x;                             // element `lane` (< cnt)
        for (int j = lane + 32; j < cnt; j += 32) {
            unsigned long long k = list[j].x;
            if (k < key[KSEL - 1]) {
                unsigned long long v = k;
#pragma unroll
                for (int s2 = 0; s2 < KSEL; ++s2) {
                    unsigned long long cur = key[s2];
                    bool lt = v < cur;
                    key[s2] = lt ? v : cur;
                    v = lt ? cur : v;
                }
            }
        }
        // ---- 8 rounds: REDUX-min merge (flat, no register bloat) ----
        unsigned long long mysel = SENT;
#pragma unroll
        for (int r = 0; r < KSEL; ++r) {
            unsigned zhi = (unsigned)(key[0] >> 32);
            unsigned mz = __reduce_min_sync(FULL, zhi);
            unsigned lo = (zhi == mz) ? (unsigned)key[0] : 0xffffffffu;
            unsigned mi = __reduce_min_sync(FULL, lo);
            unsigned long long m = ((unsigned long long)mz << 32) | mi;
            if (key[0] == m) {                      // unique owner pops
#pragma unroll
                for (int s2 = 0; s2 < KSEL - 1; ++s2) key[s2] = key[s2 + 1];
                key[KSEL - 1] = SENT;
            }
            if (lane == r) mysel = m;
        }
        if (lane < KSEL) {
            const int b = pix >> 12;
            const int pp = pix & 4095;
            const float px = 1.0f - ((float)(pp & 63) + 0.5f) * 0.03125f;
            const float py = 1.0f - ((float)(pp >> 6) + 0.5f) * 0.03125f;
            float vi, vz, vd;
            if (mysel == SENT) {
                vi = -1.0f; vz = -1.0f; vd = -1.0f;
            } else {
                unsigned pidx = (unsigned)mysel;
                float4 s = g_screen[(b << 13) + pidx];
                float dx = __fsub_rn(px, s.x);
                float dy = __fsub_rn(py, s.y);
                vd = __fadd_rn(__fmul_rn(dx, dx), __fmul_rn(dy, dy));
                vz = __uint_as_float((unsigned)(mysel >> 32));
                vi = (float)pidx;
            }
            out[o0 + lane] = vi;
            out[TSZ + o0 + lane] = vz;
            out[2 * TSZ + o0 + lane] = vd;
        }
    }

    if (lane == 0) g_cnt[pix] = 0;   // restore zero-state for next replay
}

extern "C" void kernel_launch(void* const* d_in, const int* in_sizes, int n_in,
                              void* d_out, int out_size) {
    const float* pts   = (const float*)d_in[0];  // [2,8192,3]
    const float* Rm    = (const float*)d_in[1];  // [2,3,3]
    const float* Tv    = (const float*)d_in[2];  // [2,3]
    const float* focal = (const float*)d_in[3];  // [2]
    float* out = (float*)d_out;

    project_scatter<<<BATCH * NPTS * 8 / 256, 256>>>(pts, Rm, Tv, focal);

    // PDL launch: select_k may begin its prologue while project_scatter runs;
    // it blocks at griddepcontrol.wait until A signals launch_dependents.
    cudaLaunchConfig_t cfg = {};
    cfg.gridDim = dim3(NPIX / 8);
    cfg.blockDim = dim3(256);
    cfg.dynamicSmemBytes = 0;
    cfg.stream = 0;                 // legacy default stream (same as <<<>>>)
    cudaLaunchAttribute at[1];
    at[0].id = cudaLaunchAttributeProgrammaticStreamSerialization;
    at[0].val.programmaticStreamSerializationAllowed = 1;
    cfg.attrs = at;
    cfg.numAttrs = 1;
    cudaLaunchKernelEx(&cfg, select_k, out);
}

// round 12
// speedup vs baseline: 1.0045x; 1.0045x over previous
#include <cuda_runtime.h>
#include <cstdint>

#define BATCH 2
#define NPTS 8192
#define IMGS 64
#define KSEL 8
#define RAD2 0.0025f
#define RADM 0.0501f            // conservative bbox radius
#define NPIX (BATCH * IMGS * IMGS)   // 8192
#define CAP 256                 // per-pixel capacity (hot pixel ~150; +13 sigma)
#define OUTN (3 * NPIX * KSEL)  // 196608 floats

// Static scratch (allocation-free). BSS-zero at load; select_k restores
// g_cnt to zero every launch (graph-replay invariant).
__device__ float4 g_screen[BATCH * NPTS];
__device__ int g_cnt[NPIX];
__device__ ulonglong2 g_plist[(size_t)NPIX * CAP];   // {key, d2bits} — 32 MB

// ---------------------------------------------------------------------------
// Kernel A: -1-fill the output, then project + scatter. EIGHT lanes per
// point, each owns a 1x2 sub-row of the 4x4 bbox. Ends in
// griddepcontrol.launch_dependents (PDL) so select_k releases early.
// ---------------------------------------------------------------------------
__global__ __launch_bounds__(256) void project_scatter(const float* __restrict__ pts,
                                                       const float* __restrict__ Rm,
                                                       const float* __restrict__ Tv,
                                                       const float* __restrict__ focal,
                                                       float* __restrict__ out) {
    const int gt = blockIdx.x * 256 + threadIdx.x;   // 0..131071

    // ---- sentinel fill: out[:] = -1 (coalesced float4; B only overwrites
    // selected slots). 49152 float4 over 131072 threads.
    if (gt < OUTN / 4) {
        reinterpret_cast<float4*>(out)[gt] = make_float4(-1.f, -1.f, -1.f, -1.f);
    }

    const int t = gt >> 3;                           // point id 0..16383
    const int sub = gt & 7;
    const int row = sub >> 1;                        // bbox row 0..3
    const int ch = (sub & 1) << 1;                   // bbox col pair: 0 or 2
    const int b = t >> 13;
    const int n = t & (NPTS - 1);
    const float* p = pts + (size_t)t * 3;
    const float* R = Rm + b * 9;
    const float* T = Tv + b * 3;
    float p0 = p[0], p1 = p[1], p2 = p[2];

    float v0 = __fmaf_rn(p2, R[6], __fmaf_rn(p1, R[3], __fmul_rn(p0, R[0])));
    float v1 = __fmaf_rn(p2, R[7], __fmaf_rn(p1, R[4], __fmul_rn(p0, R[1])));
    float v2 = __fmaf_rn(p2, R[8], __fmaf_rn(p1, R[5], __fmul_rn(p0, R[2])));
    v0 = __fadd_rn(v0, T[0]);
    v1 = __fadd_rn(v1, T[1]);
    float z = __fadd_rn(v2, T[2]);

    float x = -__fdiv_rn(__fmul_rn(focal[0], v0), z);
    float y = -__fdiv_rn(__fmul_rn(focal[1], v1), z);
    if (sub == 0) g_screen[t] = make_float4(x, y, z, 0.0f);  // slow-path emit data

    if (z > 0.0f) {
        // pixel centers c(i) = 1 - (i+0.5)*0.03125, decreasing in i.
        int ix0 = (int)ceilf(__fmul_rn(1.0f - (x + RADM), 32.0f) - 0.5f);
        int ix1 = (int)floorf(__fmul_rn(1.0f - (x - RADM), 32.0f) - 0.5f);
        int iy0 = (int)ceilf(__fmul_rn(1.0f - (y + RADM), 32.0f) - 0.5f);
        int iy1 = (int)floorf(__fmul_rn(1.0f - (y - RADM), 32.0f) - 0.5f);
        ix0 = max(ix0, 0); ix1 = min(ix1, IMGS - 1);
        iy0 = max(iy0, 0); iy1 = min(iy1, IMGS - 1);

        const int iy = iy0 + row;                   // this lane's bbox row
        if (iy <= iy1) {
            const unsigned long long key =
                ((unsigned long long)__float_as_uint(z) << 32) | (unsigned)n;
            float py = 1.0f - ((float)iy + 0.5f) * 0.03125f;
            float dy = __fsub_rn(py, y);
            float dy2 = __fmul_rn(dy, dy);
#pragma unroll
            for (int c = 0; c < 2; ++c) {
                int ix = ix0 + ch + c;
                bool vx = ix <= ix1;
                float px = 1.0f - ((float)ix + 0.5f) * 0.03125f;
                float dx = __fsub_rn(px, x);
                float d2 = __fadd_rn(__fmul_rn(dx, dx), dy2);
                if (vx && d2 <= RAD2) {             // exact reference predicate
                    int pix = (b << 12) + (iy << 6) + ix;
                    int pos = atomicAdd(&g_cnt[pix], 1);
                    if (pos < CAP)
                        g_plist[(size_t)pix * CAP + pos] =
                            make_ulonglong2(key, (unsigned long long)__float_as_uint(d2));
                }
            }
        }
    }

    // PDL: signal dependent kernel once this thread's writes are issued.
    asm volatile("griddepcontrol.launch_dependents;" ::: "memory");
}

// ---------------------------------------------------------------------------
// Kernel B: one warp per pixel. Output is pre-filled with -1 by kernel A, so
// B writes ONLY winning slots. cnt and list[lane] load in parallel (R10's
// measured-best chain shape); empty warps load-and-exit with zero stores.
//   cnt <= 32  : rank selection, 1 key/lane.
//   cnt <= 64  : rank selection, 2 keys/lane.
//   cnt  > 64  : per-lane sorted top-8; REDUX-min merge; gather-based emit
//                (>= 8 winners guaranteed, no sentinel check).
// Keys unique => (z, idx) ascending = jax top_k order exactly.
// ---------------------------------------------------------------------------
__global__ __launch_bounds__(256) void select_k(float* __restrict__ out) {
    const int warp = threadIdx.x >> 5;
    const int lane = threadIdx.x & 31;
    const int pix = blockIdx.x * 8 + warp;          // 0..NPIX-1
    const unsigned long long SENT = ~0ull;
    const unsigned FULL = 0xffffffffu;
    const size_t TSZ = (size_t)NPIX * KSEL;         // 65536
    const size_t o0 = (size_t)pix * KSEL;
    const ulonglong2* __restrict__ list = g_plist + (size_t)pix * CAP;

    // PDL: block before touching A-produced state.
    asm volatile("griddepcontrol.wait;" ::: "memory");

    // Parallel loads; rec only consumed under lane < cnt.
    int cnt = g_cnt[pix];
    ulonglong2 rec = list[lane];
    cnt = min(cnt, CAP);

    if (cnt == 0) return;                           // out already -1; g_cnt 0

    if (cnt <= 32) {
        // ---- single-key rank selection (flat latency) ----
        unsigned long long myk = (lane < cnt) ? rec.x : SENT;
        int rank = 0;
        for (int c = 0; c < cnt; ++c) {             // warp-uniform bound
            unsigned long long kc = __shfl_sync(FULL, myk, c);
            rank += (kc < myk) ? 1 : 0;
        }
        if (lane < cnt && rank < KSEL) {
            out[o0 + rank] = (float)(unsigned)myk;                         // idx
            out[TSZ + o0 + rank] = __uint_as_float((unsigned)(myk >> 32)); // z
            out[2 * TSZ + o0 + rank] = __uint_as_float((unsigned)rec.y);   // d2
        }
    } else if (cnt <= 64) {
        // ---- two-key rank selection ----
        unsigned long long k0 = rec.x;              // lane < 32 < cnt: valid
        unsigned long long k1 = SENT;
        unsigned d1bits = 0;
        if (lane + 32 < cnt) {
            ulonglong2 rec2 = list[lane + 32];
            k1 = rec2.x;
            d1bits = (unsigned)rec2.y;
        }
        int r0 = 0, r1 = 0;
#pragma unroll 4
        for (int c = 0; c < 32; ++c) {
            unsigned long long kc = __shfl_sync(FULL, k0, c);
            r0 += (kc < k0) ? 1 : 0;
            r1 += (kc < k1) ? 1 : 0;
        }
        for (int c = 32; c < cnt; ++c) {
            unsigned long long kc = __shfl_sync(FULL, k1, c - 32);
            r0 += (kc < k0) ? 1 : 0;
            r1 += (kc < k1) ? 1 : 0;
        }
        if (r0 < KSEL) {
            out[o0 + r0] = (float)(unsigned)k0;
            out[TSZ + o0 + r0] = __uint_as_float((unsigned)(k0 >> 32));
            out[2 * TSZ + o0 + r0] = __uint_as_float((unsigned)rec.y);
        }
        if (lane + 32 < cnt && r1 < KSEL) {
            out[o0 + r1] = (float)(unsigned)k1;
            out[TSZ + o0 + r1] = __uint_as_float((unsigned)(k1 >> 32));
            out[2 * TSZ + o0 + r1] = __uint_as_float(d1bits);
        }
    } else {
        // ---- per-lane sorted top-8 over strided scan ----
        unsigned long long key[KSEL];
#pragma unroll
        for (int i = 0; i < KSEL; ++i) key[i] = SENT;
        key[0] = rec.x;                             // element `lane` (< cnt)
        for (int j = lane + 32; j < cnt; j += 32) {
            unsigned long long k = list[j].x;
            if (k < key[KSEL - 1]) {
                unsigned long long v = k;
#pragma unroll
                for (int s2 = 0; s2 < KSEL; ++s2) {
                    unsigned long long cur = key[s2];
                    bool lt = v < cur;
                    key[s2] = lt ? v : cur;
                    v = lt ? cur : v;
                }
            }
        }
        // ---- 8 rounds: REDUX-min merge (flat) ----
        unsigned long long mysel = SENT;
#pragma unroll
        for (int r = 0; r < KSEL; ++r) {
            unsigned zhi = (unsigned)(key[0] >> 32);
            unsigned mz = __reduce_min_sync(FULL, zhi);
            unsigned lo = (zhi == mz) ? (unsigned)key[0] : 0xffffffffu;
            unsigned mi = __reduce_min_sync(FULL, lo);
            unsigned long long m = ((unsigned long long)mz << 32) | mi;
            if (key[0] == m) {                      // unique owner pops
#pragma unroll
                for (int s2 = 0; s2 < KSEL - 1; ++s2) key[s2] = key[s2 + 1];
                key[KSEL - 1] = SENT;
            }
            if (lane == r) mysel = m;
        }
        if (lane < KSEL) {                          // cnt > 64 => all valid
            const int b = pix >> 12;
            const int pp = pix & 4095;
            const float px = 1.0f - ((float)(pp & 63) + 0.5f) * 0.03125f;
            const float py = 1.0f - ((float)(pp >> 6) + 0.5f) * 0.03125f;
            unsigned pidx = (unsigned)mysel;
            float4 s = g_screen[(b << 13) + pidx];
            float dx = __fsub_rn(px, s.x);
            float dy = __fsub_rn(py, s.y);
            float vd = __fadd_rn(__fmul_rn(dx, dx), __fmul_rn(dy, dy));
            out[o0 + lane] = (float)pidx;
            out[TSZ + o0 + lane] = __uint_as_float((unsigned)(mysel >> 32));
            out[2 * TSZ + o0 + lane] = vd;
        }
    }

    if (lane == 0) g_cnt[pix] = 0;   // restore zero-state for next replay
}

extern "C" void kernel_launch(void* const* d_in, const int* in_sizes, int n_in,
                              void* d_out, int out_size) {
    const float* pts   = (const float*)d_in[0];  // [2,8192,3]
    const float* Rm    = (const float*)d_in[1];  // [2,3,3]
    const float* Tv    = (const float*)d_in[2];  // [2,3]
    const float* focal = (const float*)d_in[3];  // [2]
    float* out = (float*)d_out;

    project_scatter<<<BATCH * NPTS * 8 / 256, 256>>>(pts, Rm, Tv, focal, out);

    // PDL launch: select_k may begin its prologue while project_scatter runs;
    // it blocks at griddepcontrol.wait until A signals launch_dependents.
    cudaLaunchConfig_t cfg = {};
    cfg.gridDim = dim3(NPIX / 8);
    cfg.blockDim = dim3(256);
    cfg.dynamicSmemBytes = 0;
    cfg.stream = 0;                 // legacy default stream (same as <<<>>>)
    cudaLaunchAttribute at[1];
    at[0].id = cudaLaunchAttributeProgrammaticStreamSerialization;
    at[0].val.programmaticStreamSerializationAllowed = 1;
    cfg.attrs = at;
    cfg.numAttrs = 1;
    cudaLaunchKernelEx(&cfg, select_k, out);
}